// round 2
// baseline (speedup 1.0000x reference)
#include <cuda_runtime.h>

typedef unsigned long long u64;

#define NWIRES 12
#define DIM    4096
#define NT     256
#define BATCH  8192

// ---------- packed f32x2 helpers (Blackwell sm_100+) ----------
__device__ __forceinline__ u64 pk2(float lo, float hi){
    u64 r; asm("mov.b64 %0, {%1,%2};" : "=l"(r) : "f"(lo), "f"(hi)); return r;
}
__device__ __forceinline__ void upk2(u64 v, float& lo, float& hi){
    asm("mov.b64 {%0,%1}, %2;" : "=f"(lo), "=f"(hi) : "l"(v));
}
__device__ __forceinline__ u64 swp2(u64 v){  // (re,im) -> (im,re)
    float a,b; upk2(v,a,b); return pk2(b,a);
}
__device__ __forceinline__ u64 f2fma(u64 a, u64 b, u64 c){
    u64 d; asm("fma.rn.f32x2 %0, %1, %2, %3;" : "=l"(d) : "l"(a), "l"(b), "l"(c)); return d;
}
__device__ __forceinline__ u64 f2mul(u64 a, u64 b){
    u64 d; asm("mul.rn.f32x2 %0, %1, %2;" : "=l"(d) : "l"(a), "l"(b)); return d;
}

// linear bank swizzle: folds idx bits [4:8) and [8:12) into low nibble.
__host__ __device__ constexpr unsigned swz(unsigned x){
    return x ^ ((x >> 4) & 15u) ^ ((x >> 8) & 15u);
}

// One fused pass: 4 wires (GRP*4 .. GRP*4+3) of layer LAYER.
// Deferred-CNOT addressing:
//   layer 0: phi = id            -> mask_i = row_i = 1<<b           (b = 11-w)
//   layer 1: phi = C (CNOT chain)-> mask_i = col_b(C) = {b,b-1} (or {0})
//                                   row_i  = row_b(C^-1) = bits >= b
// Element j of the 16-coset holds logical bit_i = alpha_i ^ j_i with
// alpha_i = parity(p_base & row_i).  alpha=1 is handled by X·(RY·RX)·X = RY(-s)·RX.
template<int LAYER, int GRP, bool INIT, bool MEAS>
__device__ __forceinline__ void do_pass(u64* st, int k,
                                        const float* gc, const float* gs,
                                        const float* ec, const float* es,
                                        float* acc)
{
    // base-index expansion over non-pivot bits (pivots = the 4 mask pivot bits)
    unsigned pb;
    if (GRP == 0)      pb = (unsigned)k;                          // pivots bits 11..8
    else if (GRP == 1) pb = (unsigned)((k & 15) | ((k & 0xF0) << 4)); // pivots 7..4
    else               pb = (unsigned)(k << 4);                   // pivots 3..0
    const unsigned spb = swz(pb);

    u64 a[16];

    // compile-time masks / parity rows
    unsigned M[4], R[4];
#pragma unroll
    for (int i = 0; i < 4; i++){
        const int w = GRP*4 + i, b = 11 - w;
        M[i] = (LAYER == 0) ? (1u << b) : (b ? (3u << (b-1)) : 1u);
        R[i] = (LAYER == 0) ? (1u << b) : ((0xFFFu << b) & 0xFFFu);
    }

    if (INIT){
        // product-state init from encoding RYs: amp(p) = prod (bit? sin : cos)
        // non-pivot bits: bit z of k = physical bit z = wire 11-z
        float pr = 1.f;
#pragma unroll
        for (int z = 0; z < 8; z++)
            pr *= ((k >> z) & 1) ? es[11 - z] : ec[11 - z];
        // pivot bits: register bit i <-> M[i] = 1<<(11-i) <-> wire i
#pragma unroll
        for (int j = 0; j < 16; j++){
            float v = pr;
#pragma unroll
            for (int i = 0; i < 4; i++)
                v *= ((j >> i) & 1) ? es[i] : ec[i];
            a[j] = pk2(v, 0.f);
        }
    } else {
#pragma unroll
        for (int j = 0; j < 16; j++){
            const unsigned cj = ((j&1)?M[0]:0u) ^ ((j&2)?M[1]:0u)
                              ^ ((j&4)?M[2]:0u) ^ ((j&8)?M[3]:0u);
            a[j] = st[spb ^ swz(cj)];
        }
    }

    // 4 fused gates: per wire apply RX(theta) then RY(theta)
#pragma unroll
    for (int i = 0; i < 4; i++){
        const int w = GRP*4 + i;
        const float c = gc[LAYER*12 + w];
        const float s = gs[LAYER*12 + w];
        const int alpha = __popc(pb & R[i]) & 1;
        const float sy  = alpha ? -s : s;       // RY sign flip under X·U·X
        const u64 cc  = pk2(c,  c);
        const u64 sx  = pk2(s, -s);             // RX: v = c*u + (s,-s)*swap(u')
        const u64 syp = pk2( sy,  sy);
        const u64 syn = pk2(-sy, -sy);
#pragma unroll
        for (int j = 0; j < 16; j++){
            if (j & (1 << i)) continue;
            const int j1 = j | (1 << i);
            const u64 u0 = a[j], u1 = a[j1];
            // RX
            const u64 v0 = f2fma(sx, swp2(u1), f2mul(cc, u0));
            const u64 v1 = f2fma(sx, swp2(u0), f2mul(cc, u1));
            // RY (with per-thread sign)
            a[j]  = f2fma(syn, v1, f2mul(cc, v0));
            a[j1] = f2fma(syp, v0, f2mul(cc, v1));
        }
    }

    if (MEAS){
        // probs + signed sums. Measurement parity rows R_b = {b, b+2, ...}
        // (rows of (C^2)^-1). Over the 16-coset the sign pattern is
        // (-1)^{popc(j & t)} with t in {0,1,3,7,15} -> need W0,W1,W3,W7,W15.
        float p[16];
#pragma unroll
        for (int j = 0; j < 16; j++){
            float re, im; upk2(a[j], re, im);
            p[j] = fmaf(re, re, im*im);
        }
        float W0 = 0.f, W1 = 0.f, W3 = 0.f;
        float d1[8], d2[4], d3[2];
#pragma unroll
        for (int j = 0; j < 8; j++){
            d1[j] = p[2*j] - p[2*j+1];
            W0   += p[2*j] + p[2*j+1];
            W1   += d1[j];
        }
#pragma unroll
        for (int j = 0; j < 4; j++){ d2[j] = d1[2*j] - d1[2*j+1]; W3 += d2[j]; }
        d3[0] = d2[0] - d2[1];  d3[1] = d2[2] - d2[3];
        const float W7  = d3[0] + d3[1];
        const float W15 = d3[0] - d3[1];
        const float Wt[4] = {W1, W3, W7, W15};
#pragma unroll
        for (int w = 0; w < 12; w++){
            const int b = 11 - w;
            const unsigned Rm = (0x555u << b) & 0xFFFu;   // bits b, b+2, ...
            const float v = (w < 8) ? W0 : Wt[w - 8];
            acc[w] += (__popc(pb & Rm) & 1) ? -v : v;
        }
    } else {
#pragma unroll
        for (int j = 0; j < 16; j++){
            const unsigned cj = ((j&1)?M[0]:0u) ^ ((j&2)?M[1]:0u)
                              ^ ((j&4)?M[2]:0u) ^ ((j&8)?M[3]:0u);
            st[spb ^ swz(cj)] = a[j];
        }
    }
}

__global__ void __launch_bounds__(NT)
qsim_kernel(const float* __restrict__ x, const float* __restrict__ params,
            const float* __restrict__ hw, const float* __restrict__ hb,
            float* __restrict__ out)
{
    __shared__ u64 st[DIM];               // 32 KB state (swizzled layout)
    __shared__ float ec[12], es[12];      // encoding cos/sin (per sample)
    __shared__ float gc[24], gs[24];      // variational cos/sin (shared params)
    __shared__ float red[8][12];
    __shared__ float evec[12];

    const int b = blockIdx.x, t = threadIdx.x;

    if (t < 12){
        float sn, cs; sincosf(0.5f * x[b*12 + t], &sn, &cs);
        ec[t] = cs; es[t] = sn;
    } else if (t < 36){
        const int i = t - 12;
        float sn, cs; sincosf(0.5f * params[i], &sn, &cs);
        gc[i] = cs; gs[i] = sn;
    }
    __syncthreads();

    float acc[12];
#pragma unroll
    for (int w = 0; w < 12; w++) acc[w] = 0.f;

    do_pass<0,0,true ,false>(st, t, gc, gs, ec, es, acc); __syncthreads();
    do_pass<0,1,false,false>(st, t, gc, gs, ec, es, acc); __syncthreads();
    do_pass<0,2,false,false>(st, t, gc, gs, ec, es, acc); __syncthreads();
    do_pass<1,0,false,false>(st, t, gc, gs, ec, es, acc); __syncthreads();
    do_pass<1,1,false,false>(st, t, gc, gs, ec, es, acc); __syncthreads();
    do_pass<1,2,false,true >(st, t, gc, gs, ec, es, acc);

    // reduce 12 partial expectations across 256 threads
#pragma unroll
    for (int off = 16; off; off >>= 1)
#pragma unroll
        for (int w = 0; w < 12; w++)
            acc[w] += __shfl_xor_sync(0xffffffffu, acc[w], off);

    const int warp = t >> 5, lane = t & 31;
    if (lane == 0)
#pragma unroll
        for (int w = 0; w < 12; w++) red[warp][w] = acc[w];
    __syncthreads();

    if (t < 12){
        float e = 0.f;
#pragma unroll
        for (int r = 0; r < 8; r++) e += red[r][t];
        evec[t] = e * hw[t];
    }
    __syncthreads();

    if (t == 0){
        float o = hb[0];
#pragma unroll
        for (int w = 0; w < 12; w++) o += evec[w];
        out[b] = o;
    }
}

extern "C" void kernel_launch(void* const* d_in, const int* in_sizes, int n_in,
                              void* d_out, int out_size)
{
    const float* x      = (const float*)d_in[0];   // [8192,12]
    const float* params = (const float*)d_in[1];   // [2,12]
    const float* hw     = (const float*)d_in[2];   // [1,12]
    const float* hb     = (const float*)d_in[3];   // [1]
    float* out          = (float*)d_out;           // [8192,1]
    (void)in_sizes; (void)n_in; (void)out_size;

    qsim_kernel<<<BATCH, NT>>>(x, params, hw, hb, out);
}

// round 3
// speedup vs baseline: 39.5541x; 39.5541x over previous
#include <cuda_runtime.h>

#define NT    64
#define BATCH 8192

struct C2 { float re, im; };
__device__ __forceinline__ C2 cmul (C2 a, C2 b){ return {a.re*b.re - a.im*b.im, a.re*b.im + a.im*b.re}; }
__device__ __forceinline__ C2 cmulc(C2 a, C2 b){ /* a * conj(b) */
    return {a.re*b.re + a.im*b.im, a.im*b.re - a.re*b.im}; }
__device__ __forceinline__ C2 cadd (C2 a, C2 b){ return {a.re+b.re, a.im+b.im}; }
__device__ __forceinline__ C2 cscale(C2 a, float s){ return {a.re*s, a.im*s}; }

// Per sample: E_w = <Phi| (⊗_{j<=w} O_j) |Phi>,  Phi = CNOT-chain |⊗ phi_j>,
// Phi(q) = prod_j phi_j[q_j ^ q_{j-1}]  (bond-2 MPS).
// O_j = cos^2(t) Z + sin(t)cos(t) Y - sin(t) X,  t = params[1][j].
// phi_j = RY(t1) RX(t1) RY(x_j) |0>,             t1 = params[0][j].
// Forward sweep over wires with 2x2-complex boundary L[(ket bond, bra bond)];
// identity suffix collapses to R = [[1, X_{w+1}],[X_{w+1}, 1]],
// X_j = 2 Re(phi_j[0] conj(phi_j[1])),  X_12 := 1.
__global__ void __launch_bounds__(NT)
qexp_kernel(const float* __restrict__ x, const float* __restrict__ params,
            const float* __restrict__ hw, const float* __restrict__ hb,
            float* __restrict__ out)
{
    __shared__ float sc1[12], ss1[12];          // layer-1 half-angle cos/sin
    __shared__ float sOa[12], sOb[12], sOc[12]; // O_j Pauli coeffs (X,Y,Z)
    __shared__ float shw[12];
    __shared__ float shb;

    const int t = threadIdx.x;
    if (t < 12){
        float s, c; sincosf(0.5f * params[t], &s, &c);
        sc1[t] = c; ss1[t] = s; shw[t] = hw[t];
    } else if (t < 24){
        const int i = t - 12;
        float s, c; sincosf(params[12 + i], &s, &c);   // FULL angle for O
        sOa[i] = -s; sOb[i] = s * c; sOc[i] = c * c;
    } else if (t == 24){
        shb = hb[0];
    }
    __syncthreads();

    const int b = blockIdx.x * NT + t;
    const float* xb = x + b * 12;

    C2 L00 = {1.f, 0.f}, L01 = {0.f, 0.f}, L10 = {0.f, 0.f}, L11 = {0.f, 0.f};
    float acc = shb;

    #pragma unroll
    for (int j = 0; j < 12; j++){
        float sx, cx; __sincosf(0.5f * xb[j], &sx, &cx);
        const float c1 = sc1[j], s1 = ss1[j];
        // phi_j = RY(t1) RX(t1) (cx, sx)
        const C2 f0 = {  c1 * (c1 * cx - s1 * sx),  s1 * (s1 * cx - c1 * sx) };
        const C2 f1 = {  c1 * (s1 * cx + c1 * sx), -s1 * (s1 * sx + c1 * cx) };

        if (j > 0){
            // emit E_{j-1} using suffix closure with X_j of THIS wire
            const float Xj = 2.f * (f0.re * f1.re + f0.im * f1.im);
            const float E  = (L00.re + L11.re) + Xj * (L01.re + L10.re);
            acc = fmaf(shw[j-1], E, acc);
        }

        // M[c][q'] = sum_{c'} conj(phi[q'^c']) L[c][c']
        const C2 M00 = cadd(cmulc(L00, f0), cmulc(L01, f1));
        const C2 M01 = cadd(cmulc(L00, f1), cmulc(L01, f0));
        const C2 M10 = cadd(cmulc(L10, f0), cmulc(L11, f1));
        const C2 M11 = cadd(cmulc(L10, f1), cmulc(L11, f0));
        // N[q][q'] = sum_c phi[q^c] M[c][q']
        const C2 N00 = cadd(cmul(f0, M00), cmul(f1, M10));
        const C2 N01 = cadd(cmul(f0, M01), cmul(f1, M11));
        const C2 N10 = cadd(cmul(f1, M00), cmul(f0, M10));
        const C2 N11 = cadd(cmul(f1, M01), cmul(f0, M11));
        // L'[q][q'] = Op[q'][q] * N[q][q'];  Op = [[cc, a-ib],[a+ib, -cc]]
        const float a = sOa[j], bb = sOb[j], cc = sOc[j];
        L00 = cscale(N00,  cc);
        L11 = cscale(N11, -cc);
        const C2 op01 = {a, -bb};   // Op[0][1]
        const C2 op10 = {a,  bb};   // Op[1][0]
        L01 = cmul(op10, N01);      // q=0, q'=1 -> Op[1][0]
        L10 = cmul(op01, N10);      // q=1, q'=0 -> Op[0][1]
    }

    // E_11: empty suffix -> all four boundary entries sum (X_12 = 1)
    const float E11 = L00.re + L11.re + L01.re + L10.re;
    acc = fmaf(shw[11], E11, acc);

    out[b] = acc;
}

extern "C" void kernel_launch(void* const* d_in, const int* in_sizes, int n_in,
                              void* d_out, int out_size)
{
    const float* x      = (const float*)d_in[0];   // [8192,12]
    const float* params = (const float*)d_in[1];   // [2,12]
    const float* hw     = (const float*)d_in[2];   // [1,12]
    const float* hb     = (const float*)d_in[3];   // [1]
    float* out          = (float*)d_out;           // [8192,1]
    (void)in_sizes; (void)n_in; (void)out_size;

    qexp_kernel<<<BATCH / NT, NT>>>(x, params, hw, hb, out);
}

// round 4
// speedup vs baseline: 44.3485x; 1.1212x over previous
#include <cuda_runtime.h>

#define NT    32
#define BATCH 8192

struct C2 { float re, im; };
__device__ __forceinline__ C2 cmul (C2 a, C2 b){ return {a.re*b.re - a.im*b.im, a.re*b.im + a.im*b.re}; }
__device__ __forceinline__ C2 cmulc(C2 a, C2 b){ /* a * conj(b) */
    return {a.re*b.re + a.im*b.im, a.im*b.re - a.re*b.im}; }
__device__ __forceinline__ C2 cadd (C2 a, C2 b){ return {a.re+b.re, a.im+b.im}; }
__device__ __forceinline__ C2 cscale(C2 a, float s){ return {a.re*s, a.im*s}; }

// Per sample: E_w = <Phi| (⊗_{j<=w} O_j) |Phi>,  Phi = CNOT-chain |⊗ phi_j>,
// Phi(q) = prod_j phi_j[q_j ^ q_{j-1}]  (bond-2 MPS).
// O_j = cos^2(t) Z + sin(t)cos(t) Y - sin(t) X,  t = params[1][j].
// phi_j = RY(t1) RX(t1) RY(x_j) |0>,             t1 = params[0][j].
// Forward sweep with 2x2-complex boundary L[(ket bond, bra bond)];
// identity suffix collapses to R = [[1, X_{w+1}],[X_{w+1}, 1]],
// X_j = 2 Re(phi_j[0] conj(phi_j[1])),  X_12 := 1.
__global__ void __launch_bounds__(NT)
qexp_kernel(const float* __restrict__ x, const float* __restrict__ params,
            const float* __restrict__ hw, const float* __restrict__ hb,
            float* __restrict__ out)
{
    __shared__ float sc1[12], ss1[12];          // layer-1 half-angle cos/sin
    __shared__ float sOa[12], sOb[12], sOc[12]; // O_j Pauli coeffs (X,Y,Z)
    __shared__ float shw[12];
    __shared__ float shb;

    const int t = threadIdx.x;
    const int b = blockIdx.x * NT + t;

    // ---- issue all sample loads FIRST (three float4, MLP=3) ----
    const float4* xv = (const float4*)(x + b * 12);   // 48B row, 16B aligned
    const float4 xq0 = xv[0], xq1 = xv[1], xq2 = xv[2];

    if (t < 12){
        float s, c; sincosf(0.5f * params[t], &s, &c);
        sc1[t] = c; ss1[t] = s; shw[t] = hw[t];
    } else if (t < 24){
        const int i = t - 12;
        float s, c; sincosf(params[12 + i], &s, &c);   // FULL angle for O
        sOa[i] = -s; sOb[i] = s * c; sOc[i] = c * c;
    } else if (t == 24){
        shb = hb[0];
    }
    __syncthreads();

    const float xa[12] = { xq0.x, xq0.y, xq0.z, xq0.w,
                           xq1.x, xq1.y, xq1.z, xq1.w,
                           xq2.x, xq2.y, xq2.z, xq2.w };

    // ---- precompute phi_j for all wires (independent, high ILP) ----
    C2 F0[12], F1[12];
    float Xs[12];
    #pragma unroll
    for (int j = 0; j < 12; j++){
        float sx, cx; __sincosf(0.5f * xa[j], &sx, &cx);
        const float c1 = sc1[j], s1 = ss1[j];
        const C2 f0 = {  c1 * (c1 * cx - s1 * sx),  s1 * (s1 * cx - c1 * sx) };
        const C2 f1 = {  c1 * (s1 * cx + c1 * sx), -s1 * (s1 * sx + c1 * cx) };
        F0[j] = f0; F1[j] = f1;
        Xs[j] = 2.f * (f0.re * f1.re + f0.im * f1.im);
    }

    // ---- serial transfer-matrix sweep (registers only) ----
    C2 L00 = {1.f, 0.f}, L01 = {0.f, 0.f}, L10 = {0.f, 0.f}, L11 = {0.f, 0.f};
    float acc = shb;

    #pragma unroll
    for (int j = 0; j < 12; j++){
        const C2 f0 = F0[j], f1 = F1[j];

        if (j > 0){
            // emit E_{j-1}: suffix closure uses X of THIS wire
            const float E = (L00.re + L11.re) + Xs[j] * (L01.re + L10.re);
            acc = fmaf(shw[j-1], E, acc);
        }

        // M[c][q'] = sum_{c'} conj(phi[q'^c']) L[c][c']
        const C2 M00 = cadd(cmulc(L00, f0), cmulc(L01, f1));
        const C2 M01 = cadd(cmulc(L00, f1), cmulc(L01, f0));
        const C2 M10 = cadd(cmulc(L10, f0), cmulc(L11, f1));
        const C2 M11 = cadd(cmulc(L10, f1), cmulc(L11, f0));
        // N[q][q'] = sum_c phi[q^c] M[c][q']
        const C2 N00 = cadd(cmul(f0, M00), cmul(f1, M10));
        const C2 N01 = cadd(cmul(f0, M01), cmul(f1, M11));
        const C2 N10 = cadd(cmul(f1, M00), cmul(f0, M10));
        const C2 N11 = cadd(cmul(f1, M01), cmul(f0, M11));
        // L'[q][q'] = Op[q'][q] * N[q][q'];  Op = [[cc, a-ib],[a+ib, -cc]]
        const float a = sOa[j], bb = sOb[j], cc = sOc[j];
        L00 = cscale(N00,  cc);
        L11 = cscale(N11, -cc);
        const C2 op01 = {a, -bb};   // Op[0][1]
        const C2 op10 = {a,  bb};   // Op[1][0]
        L01 = cmul(op10, N01);      // q=0, q'=1 -> Op[1][0]
        L10 = cmul(op01, N10);      // q=1, q'=0 -> Op[0][1]
    }

    // E_11: empty suffix -> all four boundary entries sum (X_12 = 1)
    const float E11 = L00.re + L11.re + L01.re + L10.re;
    acc = fmaf(shw[11], E11, acc);

    out[b] = acc;
}

extern "C" void kernel_launch(void* const* d_in, const int* in_sizes, int n_in,
                              void* d_out, int out_size)
{
    const float* x      = (const float*)d_in[0];   // [8192,12]
    const float* params = (const float*)d_in[1];   // [2,12]
    const float* hw     = (const float*)d_in[2];   // [1,12]
    const float* hb     = (const float*)d_in[3];   // [1]
    float* out          = (float*)d_out;           // [8192,1]
    (void)in_sizes; (void)n_in; (void)out_size;

    qexp_kernel<<<BATCH / NT, NT>>>(x, params, hw, hb, out);
}

// round 5
// speedup vs baseline: 45.4974x; 1.0259x over previous
#include <cuda_runtime.h>

#define NT    128
#define BATCH 8192

struct C2 { float re, im; };
__device__ __forceinline__ C2 cmul (C2 a, C2 b){ return {a.re*b.re - a.im*b.im, a.re*b.im + a.im*b.re}; }
__device__ __forceinline__ C2 cmulc(C2 a, C2 b){ /* a * conj(b) */
    return {a.re*b.re + a.im*b.im, a.im*b.re - a.re*b.im}; }
__device__ __forceinline__ C2 cadd (C2 a, C2 b){ return {a.re+b.re, a.im+b.im}; }
__device__ __forceinline__ C2 cscale(C2 a, float s){ return {a.re*s, a.im*s}; }

// Per sample: E_w = <Phi| (⊗_{j<=w} O_j) |Phi>,  Phi = CNOT-chain |⊗ phi_j>,
// Phi(q) = prod_j phi_j[q_j ^ q_{j-1}]  (bond-2 MPS).
// O_j = cos^2(t) Z + sin(t)cos(t) Y - sin(t) X,  t = params[1][j].
// phi_j = RY(t1) RX(t1) RY(x_j) |0>,             t1 = params[0][j].
// Forward sweep with 2x2-complex boundary L[(ket bond, bra bond)];
// identity suffix collapses to R = [[1, X_{w+1}],[X_{w+1}, 1]],
// X_j = 2 Re(phi_j[0] conj(phi_j[1])),  X_12 := 1.
// No smem / no barriers: params are broadcast loads, trig recomputed per
// thread via MUFU — the whole preamble hides under the x-load epoch.
__global__ void __launch_bounds__(NT)
qexp_kernel(const float* __restrict__ x, const float* __restrict__ params,
            const float* __restrict__ hw, const float* __restrict__ hb,
            float* __restrict__ out)
{
    const int b = blockIdx.x * NT + threadIdx.x;

    // ---- issue ALL loads up front (one memory epoch, MLP ~13) ----
    const float4* xv = (const float4*)(x + b * 12);       // 48B row, 16B aligned
    const float4 xq0 = xv[0], xq1 = xv[1], xq2 = xv[2];
    const float4* pv = (const float4*)params;             // 24 floats
    const float4 p0 = pv[0], p1 = pv[1], p2 = pv[2];
    const float4 p3 = pv[3], p4 = pv[4], p5 = pv[5];
    const float4* wv = (const float4*)hw;                 // 12 floats
    const float4 w0 = wv[0], w1 = wv[1], w2 = wv[2];
    const float bias = hb[0];

    const float xa[12]  = { xq0.x,xq0.y,xq0.z,xq0.w, xq1.x,xq1.y,xq1.z,xq1.w,
                            xq2.x,xq2.y,xq2.z,xq2.w };
    const float th1[12] = { p0.x,p0.y,p0.z,p0.w, p1.x,p1.y,p1.z,p1.w,
                            p2.x,p2.y,p2.z,p2.w };
    const float th2[12] = { p3.x,p3.y,p3.z,p3.w, p4.x,p4.y,p4.z,p4.w,
                            p5.x,p5.y,p5.z,p5.w };
    const float hwa[12] = { w0.x,w0.y,w0.z,w0.w, w1.x,w1.y,w1.z,w1.w,
                            w2.x,w2.y,w2.z,w2.w };

    // ---- per-wire trig + phi_j (independent, MUFU-pipelined) ----
    C2 F0[12], F1[12];
    float Xs[12], Oa[12], Ob[12], Oc[12];
    #pragma unroll
    for (int j = 0; j < 12; j++){
        float s1, c1; __sincosf(0.5f * th1[j], &s1, &c1);
        float s2, c2; __sincosf(th2[j], &s2, &c2);       // full angle for O
        Oa[j] = -s2; Ob[j] = s2 * c2; Oc[j] = c2 * c2;
        float sx, cx; __sincosf(0.5f * xa[j], &sx, &cx);
        const C2 f0 = {  c1 * (c1 * cx - s1 * sx),  s1 * (s1 * cx - c1 * sx) };
        const C2 f1 = {  c1 * (s1 * cx + c1 * sx), -s1 * (s1 * sx + c1 * cx) };
        F0[j] = f0; F1[j] = f1;
        Xs[j] = 2.f * (f0.re * f1.re + f0.im * f1.im);
    }

    // ---- serial transfer-matrix sweep (registers only) ----
    C2 L00 = {1.f, 0.f}, L01 = {0.f, 0.f}, L10 = {0.f, 0.f}, L11 = {0.f, 0.f};
    float acc = bias;

    #pragma unroll
    for (int j = 0; j < 12; j++){
        const C2 f0 = F0[j], f1 = F1[j];

        if (j > 0){
            // emit E_{j-1}: suffix closure uses X of THIS wire
            const float E = (L00.re + L11.re) + Xs[j] * (L01.re + L10.re);
            acc = fmaf(hwa[j-1], E, acc);
        }

        // M[c][q'] = sum_{c'} conj(phi[q'^c']) L[c][c']
        const C2 M00 = cadd(cmulc(L00, f0), cmulc(L01, f1));
        const C2 M01 = cadd(cmulc(L00, f1), cmulc(L01, f0));
        const C2 M10 = cadd(cmulc(L10, f0), cmulc(L11, f1));
        const C2 M11 = cadd(cmulc(L10, f1), cmulc(L11, f0));
        // N[q][q'] = sum_c phi[q^c] M[c][q']
        const C2 N00 = cadd(cmul(f0, M00), cmul(f1, M10));
        const C2 N01 = cadd(cmul(f0, M01), cmul(f1, M11));
        const C2 N10 = cadd(cmul(f1, M00), cmul(f0, M10));
        const C2 N11 = cadd(cmul(f1, M01), cmul(f0, M11));
        // L'[q][q'] = Op[q'][q] * N[q][q'];  Op = [[cc, a-ib],[a+ib, -cc]]
        const float a = Oa[j], bb = Ob[j], cc = Oc[j];
        L00 = cscale(N00,  cc);
        L11 = cscale(N11, -cc);
        const C2 op01 = {a, -bb};   // Op[0][1]
        const C2 op10 = {a,  bb};   // Op[1][0]
        L01 = cmul(op10, N01);      // q=0, q'=1 -> Op[1][0]
        L10 = cmul(op01, N10);      // q=1, q'=0 -> Op[0][1]
    }

    // E_11: empty suffix -> all four boundary entries sum (X_12 = 1)
    const float E11 = L00.re + L11.re + L01.re + L10.re;
    acc = fmaf(hwa[11], E11, acc);

    out[b] = acc;
}

extern "C" void kernel_launch(void* const* d_in, const int* in_sizes, int n_in,
                              void* d_out, int out_size)
{
    const float* x      = (const float*)d_in[0];   // [8192,12]
    const float* params = (const float*)d_in[1];   // [2,12]
    const float* hw     = (const float*)d_in[2];   // [1,12]
    const float* hb     = (const float*)d_in[3];   // [1]
    float* out          = (float*)d_out;           // [8192,1]
    (void)in_sizes; (void)n_in; (void)out_size;

    qexp_kernel<<<BATCH / NT, NT>>>(x, params, hw, hb, out);
}